// round 16
// baseline (speedup 1.0000x reference)
#include <cuda_runtime.h>
#include <cuda_fp16.h>
#include <cstdint>

// RNN-T Joiner, fp16 tensor-core path. R13: flat grid (R11 GEMM structure),
// BK=64 with 2-stage double buffer -> half the barriers/waits per tile.
// prep (A tanh->fp16 R7 mapping, W->fp16, tail) in one launch.
// M = 160000, K = 512, N = 1024.

constexpr int Bb = 4, Tt = 400, Uu = 100, Dd = 512, Vv = 1024;
constexpr long long Mm = (long long)Bb * Tt * Uu;   // 160000 = 128*1250

#define BM 128
#define BN 128
#define BK 64
#define NCH (Dd / BK)        // 8
#define RST 72               // smem row stride in halfs (144B): conflict-free

__device__ __half A_half[(size_t)Mm * Dd];   // 164 MB scratch (sanctioned)
__device__ __half W_half[(size_t)Vv * Dd];   // 1 MB

constexpr int NA_BLOCKS = (int)(Mm * Dd / 8 / 256);   // 40000 (8 elems/thread)
constexpr int NW_BLOCKS = (Vv * Dd / 8) / 256;        // 256

__device__ __forceinline__ float fast_tanh(float x) {
    float y; asm("tanh.approx.f32 %0, %1;" : "=f"(y) : "f"(x)); return y;
}
__device__ __forceinline__ uint32_t smem_u32(const void* p) {
    uint32_t a;
    asm("{ .reg .u64 t; cvta.to.shared.u64 t, %1; cvt.u32.u64 %0, t; }" : "=r"(a) : "l"(p));
    return a;
}
__device__ __forceinline__ void mma_fp16(float* d, const uint32_t* a,
                                         uint32_t b0, uint32_t b1) {
    asm volatile(
        "mma.sync.aligned.m16n8k16.row.col.f32.f16.f16.f32 "
        "{%0,%1,%2,%3}, {%4,%5,%6,%7}, {%8,%9}, {%0,%1,%2,%3};"
        : "+f"(d[0]), "+f"(d[1]), "+f"(d[2]), "+f"(d[3])
        : "r"(a[0]), "r"(a[1]), "r"(a[2]), "r"(a[3]), "r"(b0), "r"(b1));
}
__device__ __forceinline__ void ldm_x4(uint32_t* r, uint32_t addr) {
    asm volatile("ldmatrix.sync.aligned.m8n8.x4.shared.b16 {%0,%1,%2,%3}, [%4];"
                 : "=r"(r[0]), "=r"(r[1]), "=r"(r[2]), "=r"(r[3]) : "r"(addr));
}

// ------- Phase 1: A(tanh->fp16) [R7 8-elem mapping], W->fp16, tail --------
__global__ __launch_bounds__(256)
void prep_all_kernel(const float* __restrict__ src, const float* __restrict__ tgt,
                     const float* __restrict__ W,
                     const int* __restrict__ src_len, const int* __restrict__ tgt_len,
                     float* __restrict__ out, int extras) {
    const int bid = blockIdx.x;
    const int tid = threadIdx.x;
    if (bid < NA_BLOCKS) {
        size_t idx = (size_t)bid * 256 + tid;     // one per 8 elems
        int m = (int)(idx >> 6);
        int kv = ((int)idx & 63) * 8;
        int b = m / (Tt * Uu);
        int rem = m - b * (Tt * Uu);
        int t = rem / Uu;
        int u = rem - t * Uu;
        const float* sp = src + ((size_t)b * Tt + t) * Dd + kv;
        const float* tp = tgt + ((size_t)b * Uu + u) * Dd + kv;
        float4 s0 = *reinterpret_cast<const float4*>(sp);
        float4 s1 = *reinterpret_cast<const float4*>(sp + 4);
        float4 t0 = *reinterpret_cast<const float4*>(tp);
        float4 t1 = *reinterpret_cast<const float4*>(tp + 4);
        __half2 h[4];
        h[0] = __floats2half2_rn(fast_tanh(s0.x + t0.x), fast_tanh(s0.y + t0.y));
        h[1] = __floats2half2_rn(fast_tanh(s0.z + t0.z), fast_tanh(s0.w + t0.w));
        h[2] = __floats2half2_rn(fast_tanh(s1.x + t1.x), fast_tanh(s1.y + t1.y));
        h[3] = __floats2half2_rn(fast_tanh(s1.z + t1.z), fast_tanh(s1.w + t1.w));
        *reinterpret_cast<uint4*>(&A_half[(size_t)m * Dd + kv]) =
            *reinterpret_cast<uint4*>(h);
    } else if (bid < NA_BLOCKS + NW_BLOCKS) {
        size_t idx = ((size_t)(bid - NA_BLOCKS) * 256 + tid) * 8;
        float4 w0 = *reinterpret_cast<const float4*>(W + idx);
        float4 w1 = *reinterpret_cast<const float4*>(W + idx + 4);
        __half2 h[4];
        h[0] = __floats2half2_rn(w0.x, w0.y);
        h[1] = __floats2half2_rn(w0.z, w0.w);
        h[2] = __floats2half2_rn(w1.x, w1.y);
        h[3] = __floats2half2_rn(w1.z, w1.w);
        *reinterpret_cast<uint4*>(&W_half[idx]) = *reinterpret_cast<uint4*>(h);
    } else {
        if (tid < extras) {
            size_t base = (size_t)Mm * Vv;
            if (tid < Bb) out[base + tid] = (float)src_len[tid];
            else if (tid < 2 * Bb) out[base + tid] = (float)tgt_len[tid - Bb];
            else out[base + tid] = 0.0f;
        }
    }
}

// ---------------- Phase 2: fp16 GEMM, BK=64, 2-stage ----------------
constexpr int STAGE_H = BM * RST;                   // 9216 halfs / stage
constexpr int SMEM_TOTAL = 2 * 2 * STAGE_H * 2;     // A + B, 2 stages = 73728 B

__global__ __launch_bounds__(256, 2)
void joiner_gemm_fp16(const float* __restrict__ bias, float* __restrict__ out) {
    extern __shared__ __half sm[];
    __half* Asm = sm;                     // 2 stages
    __half* Bsm = sm + 2 * STAGE_H;       // 2 stages

    const int tid = threadIdx.x;
    const int wid = tid >> 5, lid = tid & 31;
    const int g = lid >> 2, c = lid & 3;
    const int wm = wid >> 2, wn = wid & 3;           // warp grid 2(m) x 4(n)
    // n-block fastest -> 8 CTAs share one A m-chunk in L2
    const size_t m0 = (size_t)blockIdx.y * BM;
    const int n0 = blockIdx.x * BN;

    // producer mapping: 2 threads per row, 32 halfs (64B = 4x16B) each
    const int r = tid >> 1;
    const int h = tid & 1;
    const __half* agp = A_half + (m0 + r) * Dd + h * 32;
    const __half* bgp = W_half + (size_t)(n0 + r) * Dd + h * 32;
    const uint32_t a_dst0 = smem_u32(Asm) + (uint32_t)(r * (RST * 2) + h * 64);
    const uint32_t b_dst0 = smem_u32(Bsm) + (uint32_t)(r * (RST * 2) + h * 64);

    // ldmatrix per-lane source addresses (stage 0 base)
    const uint32_t a_lm = smem_u32(Asm)
        + (uint32_t)((wm * 64 + (lid & 15)) * (RST * 2) + ((lid >> 4) & 1) * 16);
    const uint32_t b_lm = smem_u32(Bsm)
        + (uint32_t)((wn * 32 + ((lid >> 4) & 1) * 8 + (lid & 7)) * (RST * 2)
                     + ((lid >> 3) & 1) * 16);

    float acc[4][4][4];
#pragma unroll
    for (int mt = 0; mt < 4; mt++)
#pragma unroll
        for (int nt = 0; nt < 4; nt++)
#pragma unroll
            for (int i = 0; i < 4; i++) acc[mt][nt][i] = 0.0f;

#define ISSUE_STAGE(CH) do {                                                    \
        int st_ = (CH) & 1;                                                     \
        const __half* ag_ = agp + (CH) * BK;                                    \
        const __half* bg_ = bgp + (CH) * BK;                                    \
        uint32_t ad_ = a_dst0 + st_ * (STAGE_H * 2);                            \
        uint32_t bd_ = b_dst0 + st_ * (STAGE_H * 2);                            \
        asm volatile(                                                           \
            "cp.async.cg.shared.global [%0], [%1], 16;\n"                       \
            "cp.async.cg.shared.global [%2], [%3], 16;\n"                       \
            "cp.async.cg.shared.global [%4], [%5], 16;\n"                       \
            "cp.async.cg.shared.global [%6], [%7], 16;\n"                       \
            "cp.async.cg.shared.global [%8], [%9], 16;\n"                       \
            "cp.async.cg.shared.global [%10], [%11], 16;\n"                     \
            "cp.async.cg.shared.global [%12], [%13], 16;\n"                     \
            "cp.async.cg.shared.global [%14], [%15], 16;\n"                     \
            "cp.async.commit_group;"                                            \
            :: "r"(ad_), "l"(ag_), "r"(ad_ + 16), "l"(ag_ + 8),                 \
               "r"(ad_ + 32), "l"(ag_ + 16), "r"(ad_ + 48), "l"(ag_ + 24),      \
               "r"(bd_), "l"(bg_), "r"(bd_ + 16), "l"(bg_ + 8),                 \
               "r"(bd_ + 32), "l"(bg_ + 16), "r"(bd_ + 48), "l"(bg_ + 24)       \
            : "memory");                                                        \
    } while (0)

    ISSUE_STAGE(0);

#pragma unroll
    for (int ch = 0; ch < NCH; ch++) {
        asm volatile("cp.async.wait_group 0;" ::: "memory");
        __syncthreads();
        if (ch + 1 < NCH) ISSUE_STAGE(ch + 1);

        const int st = ch & 1;
        const uint32_t a_st = a_lm + st * (STAGE_H * 2);
        const uint32_t b_st = b_lm + st * (STAGE_H * 2);
#pragma unroll
        for (int ks = 0; ks < 4; ks++) {
            const int kbB = ks * 32;   // byte offset: 16 halfs per k-step
            uint32_t a[4][4];
#pragma unroll
            for (int mt = 0; mt < 4; mt++)
                ldm_x4(a[mt], a_st + mt * 16 * (RST * 2) + kbB);
            uint32_t b[2][4];
            ldm_x4(b[0], b_st + kbB);                    // nt 0,1
            ldm_x4(b[1], b_st + 16 * (RST * 2) + kbB);   // nt 2,3
#pragma unroll
            for (int nt = 0; nt < 4; nt++) {
                uint32_t b0 = b[nt >> 1][(nt & 1) * 2];
                uint32_t b1 = b[nt >> 1][(nt & 1) * 2 + 1];
#pragma unroll
                for (int mt = 0; mt < 4; mt++)
                    mma_fp16(acc[mt][nt], a[mt], b0, b1);
            }
        }
    }

    // ---- epilogue: bias + float2 stores ----
#pragma unroll
    for (int nt = 0; nt < 4; nt++) {
        const int col = n0 + wn * 32 + nt * 8 + 2 * c;
        const float2 bz = *reinterpret_cast<const float2*>(bias + col);
#pragma unroll
        for (int mt = 0; mt < 4; mt++) {
            const size_t row = m0 + wm * 64 + mt * 16 + g;
            float2 o1, o2;
            o1.x = acc[mt][nt][0] + bz.x;
            o1.y = acc[mt][nt][1] + bz.y;
            o2.x = acc[mt][nt][2] + bz.x;
            o2.y = acc[mt][nt][3] + bz.y;
            *reinterpret_cast<float2*>(out + row * Vv + col) = o1;
            *reinterpret_cast<float2*>(out + (row + 8) * Vv + col) = o2;
        }
    }
}

extern "C" void kernel_launch(void* const* d_in, const int* in_sizes, int n_in,
                              void* d_out, int out_size) {
    const float* src     = (const float*)d_in[0];
    const int*   src_len = (const int*)d_in[1];
    const float* tgt     = (const float*)d_in[2];
    const int*   tgt_len = (const int*)d_in[3];
    const float* W       = (const float*)d_in[4];
    const float* bias    = (const float*)d_in[5];
    float* out = (float*)d_out;

    long long extras_ll = (long long)out_size - (long long)Mm * Vv;
    int extras = (int)(extras_ll < 0 ? 0 : (extras_ll > 256 ? 256 : extras_ll));

    prep_all_kernel<<<NA_BLOCKS + NW_BLOCKS + 1, 256>>>(
        src, tgt, W, src_len, tgt_len, out, extras);

    cudaFuncSetAttribute(joiner_gemm_fp16,
                         cudaFuncAttributeMaxDynamicSharedMemorySize, SMEM_TOTAL);
    dim3 grid(Vv / BN, (unsigned)(Mm / BM));   // 8 x 1250, n fastest
    joiner_gemm_fp16<<<grid, 256, SMEM_TOTAL>>>(bias, out);
}

// round 17
// speedup vs baseline: 1.6888x; 1.6888x over previous
#include <cuda_runtime.h>
#include <cuda_fp16.h>
#include <cstdint>

// RNN-T Joiner, fp16 tensor-core path. R17: R12 prep (8-elem mapping, single
// launch) + R11 GEMM (best known: BK=32, flat grid) deepened to 5 cp.async
// stages (4-chunk load lead), streaming (.cs) stores for out and A_half.
// M = 160000, K = 512, N = 1024.

constexpr int Bb = 4, Tt = 400, Uu = 100, Dd = 512, Vv = 1024;
constexpr long long Mm = (long long)Bb * Tt * Uu;   // 160000 = 128*1250

#define BM 128
#define BN 128
#define BK 32
#define NCH (Dd / BK)        // 16
#define STG 5                // cp.async stages (4 chunks in flight)
#define RST 40               // smem row stride in halfs (80B): conflict-free

__device__ __half A_half[(size_t)Mm * Dd];   // 164 MB scratch (sanctioned)
__device__ __half W_half[(size_t)Vv * Dd];   // 1 MB

constexpr int NA_BLOCKS = (int)(Mm * Dd / 8 / 256);   // 40000 (8 elems/thread)
constexpr int NW_BLOCKS = (Vv * Dd / 8) / 256;        // 256

__device__ __forceinline__ float fast_tanh(float x) {
    float y; asm("tanh.approx.f32 %0, %1;" : "=f"(y) : "f"(x)); return y;
}
__device__ __forceinline__ uint32_t smem_u32(const void* p) {
    uint32_t a;
    asm("{ .reg .u64 t; cvta.to.shared.u64 t, %1; cvt.u32.u64 %0, t; }" : "=r"(a) : "l"(p));
    return a;
}
__device__ __forceinline__ void mma_fp16(float* d, const uint32_t* a,
                                         uint32_t b0, uint32_t b1) {
    asm volatile(
        "mma.sync.aligned.m16n8k16.row.col.f32.f16.f16.f32 "
        "{%0,%1,%2,%3}, {%4,%5,%6,%7}, {%8,%9}, {%0,%1,%2,%3};"
        : "+f"(d[0]), "+f"(d[1]), "+f"(d[2]), "+f"(d[3])
        : "r"(a[0]), "r"(a[1]), "r"(a[2]), "r"(a[3]), "r"(b0), "r"(b1));
}
__device__ __forceinline__ void ldm_x4(uint32_t* r, uint32_t addr) {
    asm volatile("ldmatrix.sync.aligned.m8n8.x4.shared.b16 {%0,%1,%2,%3}, [%4];"
                 : "=r"(r[0]), "=r"(r[1]), "=r"(r[2]), "=r"(r[3]) : "r"(addr));
}
__device__ __forceinline__ void stg_cs_v4(void* p, uint4 v) {
    asm volatile("st.global.cs.v4.u32 [%0], {%1,%2,%3,%4};"
                 :: "l"(p), "r"(v.x), "r"(v.y), "r"(v.z), "r"(v.w) : "memory");
}
__device__ __forceinline__ void stg_cs_v2f(void* p, float2 v) {
    asm volatile("st.global.cs.v2.f32 [%0], {%1,%2};"
                 :: "l"(p), "f"(v.x), "f"(v.y) : "memory");
}

// ------- Phase 1: A(tanh->fp16) [8-elem mapping], W->fp16, tail --------
__global__ __launch_bounds__(256)
void prep_all_kernel(const float* __restrict__ src, const float* __restrict__ tgt,
                     const float* __restrict__ W,
                     const int* __restrict__ src_len, const int* __restrict__ tgt_len,
                     float* __restrict__ out, int extras) {
    const int bid = blockIdx.x;
    const int tid = threadIdx.x;
    if (bid < NA_BLOCKS) {
        size_t idx = (size_t)bid * 256 + tid;     // one per 8 elems
        int m = (int)(idx >> 6);
        int kv = ((int)idx & 63) * 8;
        int b = m / (Tt * Uu);
        int rem = m - b * (Tt * Uu);
        int t = rem / Uu;
        int u = rem - t * Uu;
        const float* sp = src + ((size_t)b * Tt + t) * Dd + kv;
        const float* tp = tgt + ((size_t)b * Uu + u) * Dd + kv;
        float4 s0 = *reinterpret_cast<const float4*>(sp);
        float4 s1 = *reinterpret_cast<const float4*>(sp + 4);
        float4 t0 = *reinterpret_cast<const float4*>(tp);
        float4 t1 = *reinterpret_cast<const float4*>(tp + 4);
        __half2 h[4];
        h[0] = __floats2half2_rn(fast_tanh(s0.x + t0.x), fast_tanh(s0.y + t0.y));
        h[1] = __floats2half2_rn(fast_tanh(s0.z + t0.z), fast_tanh(s0.w + t0.w));
        h[2] = __floats2half2_rn(fast_tanh(s1.x + t1.x), fast_tanh(s1.y + t1.y));
        h[3] = __floats2half2_rn(fast_tanh(s1.z + t1.z), fast_tanh(s1.w + t1.w));
        stg_cs_v4(&A_half[(size_t)m * Dd + kv], *reinterpret_cast<uint4*>(h));
    } else if (bid < NA_BLOCKS + NW_BLOCKS) {
        size_t idx = ((size_t)(bid - NA_BLOCKS) * 256 + tid) * 8;
        float4 w0 = *reinterpret_cast<const float4*>(W + idx);
        float4 w1 = *reinterpret_cast<const float4*>(W + idx + 4);
        __half2 h[4];
        h[0] = __floats2half2_rn(w0.x, w0.y);
        h[1] = __floats2half2_rn(w0.z, w0.w);
        h[2] = __floats2half2_rn(w1.x, w1.y);
        h[3] = __floats2half2_rn(w1.z, w1.w);
        *reinterpret_cast<uint4*>(&W_half[idx]) = *reinterpret_cast<uint4*>(h);
    } else {
        if (tid < extras) {
            size_t base = (size_t)Mm * Vv;
            if (tid < Bb) out[base + tid] = (float)src_len[tid];
            else if (tid < 2 * Bb) out[base + tid] = (float)tgt_len[tid - Bb];
            else out[base + tid] = 0.0f;
        }
    }
}

// ---------------- Phase 2: fp16 GEMM, BK=32, 5-stage ----------------
constexpr int STAGE_H = BM * RST;                    // 5120 halfs / stage
constexpr int SMEM_TOTAL = 2 * STG * STAGE_H * 2;    // A + B = 102400 B

__global__ __launch_bounds__(256, 2)
void joiner_gemm_fp16(const float* __restrict__ bias, float* __restrict__ out) {
    extern __shared__ __half sm[];
    __half* Asm = sm;
    __half* Bsm = sm + STG * STAGE_H;

    const int tid = threadIdx.x;
    const int wid = tid >> 5, lid = tid & 31;
    const int g = lid >> 2, c = lid & 3;
    const int wm = wid >> 2, wn = wid & 3;           // warp grid 2(m) x 4(n)
    // n-block fastest -> 8 CTAs share one A m-chunk in L2
    const size_t m0 = (size_t)blockIdx.y * BM;
    const int n0 = blockIdx.x * BN;

    const int r = tid >> 1;
    const int h = tid & 1;
    const __half* agp = A_half + (m0 + r) * Dd + h * 16;
    const __half* bgp = W_half + (size_t)(n0 + r) * Dd + h * 16;
    const uint32_t a_dst0 = smem_u32(Asm) + (uint32_t)(r * (RST * 2) + h * 32);
    const uint32_t b_dst0 = smem_u32(Bsm) + (uint32_t)(r * (RST * 2) + h * 32);

    const uint32_t a_lm = smem_u32(Asm)
        + (uint32_t)((wm * 64 + (lid & 15)) * (RST * 2) + ((lid >> 4) & 1) * 16);
    const uint32_t b_lm = smem_u32(Bsm)
        + (uint32_t)((wn * 32 + ((lid >> 4) & 1) * 8 + (lid & 7)) * (RST * 2)
                     + ((lid >> 3) & 1) * 16);

    float acc[4][4][4];
#pragma unroll
    for (int mt = 0; mt < 4; mt++)
#pragma unroll
        for (int nt = 0; nt < 4; nt++)
#pragma unroll
            for (int i = 0; i < 4; i++) acc[mt][nt][i] = 0.0f;

#define ISSUE_STAGE(CH) do {                                                    \
        int st_ = (CH) % STG;                                                   \
        const __half* ag_ = agp + (CH) * BK;                                    \
        const __half* bg_ = bgp + (CH) * BK;                                    \
        uint32_t ad_ = a_dst0 + st_ * (STAGE_H * 2);                            \
        uint32_t bd_ = b_dst0 + st_ * (STAGE_H * 2);                            \
        asm volatile(                                                           \
            "cp.async.cg.shared.global [%0], [%1], 16;\n"                       \
            "cp.async.cg.shared.global [%2], [%3], 16;\n"                       \
            "cp.async.cg.shared.global [%4], [%5], 16;\n"                       \
            "cp.async.cg.shared.global [%6], [%7], 16;\n"                       \
            "cp.async.commit_group;"                                            \
            :: "r"(ad_), "l"(ag_), "r"(ad_ + 16), "l"(ag_ + 8),                 \
               "r"(bd_), "l"(bg_), "r"(bd_ + 16), "l"(bg_ + 8) : "memory");     \
    } while (0)

    ISSUE_STAGE(0); ISSUE_STAGE(1); ISSUE_STAGE(2); ISSUE_STAGE(3);

#pragma unroll
    for (int ch = 0; ch < NCH; ch++) {
        const int rem = NCH - 1 - ch;
        if (rem >= 3)      asm volatile("cp.async.wait_group 3;" ::: "memory");
        else if (rem == 2) asm volatile("cp.async.wait_group 2;" ::: "memory");
        else if (rem == 1) asm volatile("cp.async.wait_group 1;" ::: "memory");
        else               asm volatile("cp.async.wait_group 0;" ::: "memory");
        __syncthreads();
        if (ch + 4 < NCH) ISSUE_STAGE(ch + 4);

        const int st = ch % STG;
        const uint32_t a_st = a_lm + st * (STAGE_H * 2);
        const uint32_t b_st = b_lm + st * (STAGE_H * 2);
#pragma unroll
        for (int ks = 0; ks < 2; ks++) {
            const int kbB = ks * 32;   // byte offset: 16 halfs
            uint32_t a[4][4];
#pragma unroll
            for (int mt = 0; mt < 4; mt++)
                ldm_x4(a[mt], a_st + mt * 16 * (RST * 2) + kbB);
            uint32_t b[2][4];
            ldm_x4(b[0], b_st + kbB);                    // nt 0,1
            ldm_x4(b[1], b_st + 16 * (RST * 2) + kbB);   // nt 2,3
#pragma unroll
            for (int nt = 0; nt < 4; nt++) {
                uint32_t b0 = b[nt >> 1][(nt & 1) * 2];
                uint32_t b1 = b[nt >> 1][(nt & 1) * 2 + 1];
#pragma unroll
                for (int mt = 0; mt < 4; mt++)
                    mma_fp16(acc[mt][nt], a[mt], b0, b1);
            }
        }
    }

    // ---- epilogue: bias + streaming float2 stores ----
#pragma unroll
    for (int nt = 0; nt < 4; nt++) {
        const int col = n0 + wn * 32 + nt * 8 + 2 * c;
        const float2 bz = *reinterpret_cast<const float2*>(bias + col);
#pragma unroll
        for (int mt = 0; mt < 4; mt++) {
            const size_t row = m0 + wm * 64 + mt * 16 + g;
            float2 o1, o2;
            o1.x = acc[mt][nt][0] + bz.x;
            o1.y = acc[mt][nt][1] + bz.y;
            o2.x = acc[mt][nt][2] + bz.x;
            o2.y = acc[mt][nt][3] + bz.y;
            stg_cs_v2f(out + row * Vv + col, o1);
            stg_cs_v2f(out + (row + 8) * Vv + col, o2);
        }
    }
}

extern "C" void kernel_launch(void* const* d_in, const int* in_sizes, int n_in,
                              void* d_out, int out_size) {
    const float* src     = (const float*)d_in[0];
    const int*   src_len = (const int*)d_in[1];
    const float* tgt     = (const float*)d_in[2];
    const int*   tgt_len = (const int*)d_in[3];
    const float* W       = (const float*)d_in[4];
    const float* bias    = (const float*)d_in[5];
    float* out = (float*)d_out;

    long long extras_ll = (long long)out_size - (long long)Mm * Vv;
    int extras = (int)(extras_ll < 0 ? 0 : (extras_ll > 256 ? 256 : extras_ll));

    prep_all_kernel<<<NA_BLOCKS + NW_BLOCKS + 1, 256>>>(
        src, tgt, W, src_len, tgt_len, out, extras);

    cudaFuncSetAttribute(joiner_gemm_fp16,
                         cudaFuncAttributeMaxDynamicSharedMemorySize, SMEM_TOTAL);
    dim3 grid(Vv / BN, (unsigned)(Mm / BM));   // 8 x 1250, n fastest
    joiner_gemm_fp16<<<grid, 256, SMEM_TOTAL>>>(bias, out);
}